// round 9
// baseline (speedup 1.0000x reference)
#include <cuda_runtime.h>
#include <cstdint>

// ---------------------------------------------------------------------------
// DiffractiveLayer_pixel: ifft2(fft2(waves)*h) * gumbel-selected phase/amp,
// then 10x10 pixel expansion (8x8 live center).
//
//   temp = Wc @ ( h ∘ (W @ X @ W) ) @ Wc / S^2      (W = 200x200 DFT matrix)
//   ptrig[s1,s2] from threefry/gumbel argmax, matching jax.random.key(42)
//   with jax_threefry_partitionable=True (modern JAX default):
//     split:       key_i = cipher(key, hi=0, lo=i)   (both output words)
//     random_bits: elem i -> o0 ^ o1 of cipher(key, hi=0, lo=i)
// ---------------------------------------------------------------------------

#define SDIM 200
#define NBATCH 16
#define SS 40000

__device__ float2 g_W[SS];              // DFT matrix, exp(-2*pi*i*f*r/200)
__device__ float2 g_bufA[NBATCH * SS];  // ping
__device__ float2 g_bufB[NBATCH * SS];  // pong
__device__ float2 g_ptrig[SS];          // amp * (cos+isin)

// ------------------------------ threefry2x32 -------------------------------
__host__ __device__ __forceinline__ uint32_t tf_rotl(uint32_t x, int r) {
    return (x << r) | (x >> (32 - r));
}

__host__ __device__ __forceinline__ void threefry2x32(
    uint32_t k0, uint32_t k1, uint32_t x0, uint32_t x1,
    uint32_t& o0, uint32_t& o1)
{
    uint32_t ks2 = k0 ^ k1 ^ 0x1BD11BDAu;
    x0 += k0; x1 += k1;
#define TF_R(r) { x0 += x1; x1 = tf_rotl(x1, r); x1 ^= x0; }
    TF_R(13) TF_R(15) TF_R(26) TF_R(6)   x0 += k1;  x1 += ks2 + 1u;
    TF_R(17) TF_R(29) TF_R(16) TF_R(24)  x0 += ks2; x1 += k0 + 2u;
    TF_R(13) TF_R(15) TF_R(26) TF_R(6)   x0 += k0;  x1 += k1 + 3u;
    TF_R(17) TF_R(29) TF_R(16) TF_R(24)  x0 += k1;  x1 += ks2 + 4u;
    TF_R(13) TF_R(15) TF_R(26) TF_R(6)   x0 += ks2; x1 += k0 + 5u;
#undef TF_R
    o0 = x0; o1 = x1;
}

// ----------------------- FFMA-only accurate logf ---------------------------
// cephes-style logf (~1 ulp): avoids MUFU (41M logs would serialize on MUFU).
__device__ __forceinline__ float flogf(float x) {
    int ix = __float_as_int(x);
    int e = (ix >> 23) - 126;                      // x = m * 2^e, m in [0.5,1)
    float m = __int_as_float((ix & 0x007fffff) | 0x3f000000);
    if (m < 0.70710678f) { m = m + m; e -= 1; }    // m in [sqrt(.5), sqrt(2))
    float f = m - 1.0f;
    float z = f * f;
    float p =            7.0376836292e-2f;
    p = fmaf(p, f, -1.1514610310e-1f);
    p = fmaf(p, f,  1.1676998740e-1f);
    p = fmaf(p, f, -1.2420140846e-1f);
    p = fmaf(p, f,  1.4249322787e-1f);
    p = fmaf(p, f, -1.6668057665e-1f);
    p = fmaf(p, f,  2.0000714765e-1f);
    p = fmaf(p, f, -2.4999993993e-1f);
    p = fmaf(p, f,  3.3333331174e-1f);
    float y = f * z * p;
    float fe = (float)e;
    y = fmaf(fe, -2.12194440e-4f, y);
    y = fmaf(-0.5f, z, y);
    float r = f + y;
    r = fmaf(fe, 0.693359375f, r);
    return r;
}

// bits -> gumbel noise, matching jax.random.uniform(key, ..., 1e-10, 1.0)
__device__ __forceinline__ float gumbel_from_bits(uint32_t bits) {
    float f = __uint_as_float((bits >> 9) | 0x3f800000u) - 1.0f;  // [0,1)
    float u = f + 1e-10f;            // (maxval-minval) rounds to 1.0f in fp32
    float nl = -flogf(u);            // (0, 23.03]
    return -flogf(nl);
}

// ------------------------------- init W ------------------------------------
__global__ void init_W_kernel() {
    int idx = blockIdx.x * 256 + threadIdx.x;
    if (idx < SS) {
        int f = idx / SDIM, r = idx - f * SDIM;
        int k = (f * r) % SDIM;                    // exact integer reduction
        float s, c;
        sincospif(-(float)k * 0.01f, &s, &c);      // angle = -2*pi*k/200
        g_W[idx] = make_float2(c, s);
    }
}

// --------------------------- gumbel argmax ---------------------------------
// Partitionable threefry: element i (row-major over (200,200,256)) draws
// bits = o0 ^ o1 of cipher(key, x0=0, x1=i). One block = one pixel (256 ch).
__global__ void __launch_bounds__(256) gumbel_kernel(
    const float* __restrict__ volt, const float* __restrict__ pf,
    const float* __restrict__ itf,
    uint32_t k1a, uint32_t k1b, uint32_t k2a, uint32_t k2b)
{
    int p = blockIdx.x;           // 0..39999
    int t = threadIdx.x;
    uint32_t i = (uint32_t)(p * 256 + t);

    uint32_t a0, a1, b0, b1;
    threefry2x32(k1a, k1b, 0u, i, a0, a1);   // key1: phase
    threefry2x32(k2a, k2b, 0u, i, b0, b1);   // key2: amplitude

    float v = volt[p * 256 + t];

    float sc[2];
    sc[0] = v + gumbel_from_bits(a0 ^ a1);   // phase score
    sc[1] = v + gumbel_from_bits(b0 ^ b1);   // amplitude score
    int idx[2] = {t, t};

    // warp bfly argmax (first-index tiebreak), then cross-warp in shared
#pragma unroll
    for (int c = 0; c < 2; c++) {
        float vv = sc[c]; int ii = idx[c];
#pragma unroll
        for (int d = 16; d >= 1; d >>= 1) {
            float v2 = __shfl_xor_sync(0xffffffffu, vv, d);
            int   i2 = __shfl_xor_sync(0xffffffffu, ii, d);
            if (v2 > vv || (v2 == vv && i2 < ii)) { vv = v2; ii = i2; }
        }
        sc[c] = vv; idx[c] = ii;
    }

    __shared__ float swv[2][8];
    __shared__ int   swi[2][8];
    int warp = t >> 5;
    if ((t & 31) == 0) {
#pragma unroll
        for (int c = 0; c < 2; c++) { swv[c][warp] = sc[c]; swi[c][warp] = idx[c]; }
    }
    __syncthreads();

    if (t == 0) {
        int win[2];
#pragma unroll
        for (int c = 0; c < 2; c++) {
            float vv = swv[c][0]; int ii = swi[c][0];
#pragma unroll
            for (int w = 1; w < 8; w++) {
                float v2 = swv[c][w]; int i2 = swi[c][w];
                if (v2 > vv || (v2 == vv && i2 < ii)) { vv = v2; ii = i2; }
            }
            win[c] = ii;
        }
        float s, c0;
        float ph = pf[win[0]];
        float amp = itf[win[1]] * 6.0f;
        sincosf(ph, &s, &c0);
        g_ptrig[p] = make_float2(amp * c0, amp * s);
    }
}

// ------------------------------ complex GEMMs ------------------------------
__device__ __forceinline__ float2 cmul(float2 a, float2 b) {
    return make_float2(a.x * b.x - a.y * b.y, a.x * b.y + a.y * b.x);
}

// LEFT: C[b] = Wop @ X[b].  M=200 (rows of W), merged N=(b,c)=3200, K=200.
// STAGE 1: X from waves (wr,wi), dst g_bufB, no conj.
// STAGE 3: X = g_bufA, dst g_bufB, conj(W).
template<int STAGE>
__global__ void __launch_bounds__(256) gemm_left_kernel(
    const float* __restrict__ wr, const float* __restrict__ wi)
{
    constexpr bool CONJW = (STAGE == 3);
    constexpr bool FROMW = (STAGE == 1);
    const float2* __restrict__ X = g_bufA;
    float2* __restrict__ C = g_bufB;

    __shared__ float2 As[25][40];   // As[kk][i] = Wop[i0+i][k0+kk]
    __shared__ float2 Bs[25][64];   // Bs[kk][jl] = X[b][k0+kk][j]

    int tid = threadIdx.x;
    int tn = tid & 31, tm = tid >> 5;
    int j0 = blockIdx.x * 64;       // merged columns: 50 tiles * 64 = 3200
    int i0 = blockIdx.y * 40;       // rows: 5 tiles * 40 = 200

    float2 acc[5][2];
#pragma unroll
    for (int mi = 0; mi < 5; mi++)
#pragma unroll
        for (int ni = 0; ni < 2; ni++) acc[mi][ni] = make_float2(0.f, 0.f);

    for (int k0 = 0; k0 < 200; k0 += 25) {
        for (int t2 = tid; t2 < 25 * 40; t2 += 256) {
            int i = t2 / 25, kk = t2 - i * 25;
            float2 w = g_W[(i0 + i) * 200 + k0 + kk];
            if (CONJW) w.y = -w.y;
            As[kk][i] = w;
        }
        for (int t2 = tid; t2 < 25 * 64; t2 += 256) {
            int kk = t2 >> 6, jl = t2 & 63;
            int jc = j0 + jl;
            int b = jc / 200;
            int jj = jc - b * 200;
            int g = b * SS + (k0 + kk) * 200 + jj;
            float2 v;
            if (FROMW) { v.x = wr[g]; v.y = wi[g]; } else { v = X[g]; }
            Bs[kk][jl] = v;
        }
        __syncthreads();
#pragma unroll
        for (int kk = 0; kk < 25; kk++) {
            float2 a[5], bv[2];
#pragma unroll
            for (int mi = 0; mi < 5; mi++) a[mi] = As[kk][tm + 8 * mi];
#pragma unroll
            for (int ni = 0; ni < 2; ni++) bv[ni] = Bs[kk][tn + 32 * ni];
#pragma unroll
            for (int mi = 0; mi < 5; mi++)
#pragma unroll
                for (int ni = 0; ni < 2; ni++) {
                    acc[mi][ni].x = fmaf(a[mi].x, bv[ni].x, acc[mi][ni].x);
                    acc[mi][ni].x = fmaf(-a[mi].y, bv[ni].y, acc[mi][ni].x);
                    acc[mi][ni].y = fmaf(a[mi].x, bv[ni].y, acc[mi][ni].y);
                    acc[mi][ni].y = fmaf(a[mi].y, bv[ni].x, acc[mi][ni].y);
                }
        }
        __syncthreads();
    }
#pragma unroll
    for (int mi = 0; mi < 5; mi++) {
        int i = i0 + tm + 8 * mi;
#pragma unroll
        for (int ni = 0; ni < 2; ni++) {
            int jc = j0 + tn + 32 * ni;
            int b = jc / 200;
            int jj = jc - b * 200;
            C[b * SS + i * 200 + jj] = acc[mi][ni];
        }
    }
}

// RIGHT: C[b] = X[b] @ Wop.  merged M=(b,i)=3200, N=200, K=200.
// STAGE 2: src g_bufB -> dst g_bufA, no conj, epilogue *= h.
// STAGE 4: src g_bufB -> dst g_bufA, conj(W), epilogue *= ptrig / S^2.
template<int STAGE>
__global__ void __launch_bounds__(256) gemm_right_kernel(
    const float* __restrict__ hr, const float* __restrict__ hi)
{
    constexpr bool CONJW = (STAGE == 4);
    const float2* __restrict__ X = g_bufB;
    float2* __restrict__ C = g_bufA;

    __shared__ float2 Xs[25][64];   // Xs[kk][rl] = X[(r0+rl)][k0+kk]
    __shared__ float2 Ws[25][40];   // Ws[kk][j]  = Wop[k0+kk][j0+j]

    int tid = threadIdx.x;
    int tc = tid & 7, tr = tid >> 3;
    int j0 = blockIdx.x * 40;       // cols: 5 tiles * 40 = 200
    int r0 = blockIdx.y * 64;       // merged rows: 50 tiles * 64 = 3200

    float2 acc[2][5];
#pragma unroll
    for (int mi = 0; mi < 2; mi++)
#pragma unroll
        for (int ni = 0; ni < 5; ni++) acc[mi][ni] = make_float2(0.f, 0.f);

    for (int k0 = 0; k0 < 200; k0 += 25) {
        for (int t2 = tid; t2 < 64 * 25; t2 += 256) {
            int rl = t2 / 25, kk = t2 - rl * 25;
            Xs[kk][rl] = X[(r0 + rl) * 200 + k0 + kk];
        }
        for (int t2 = tid; t2 < 25 * 40; t2 += 256) {
            int kk = t2 / 40, jj = t2 - kk * 40;
            float2 w = g_W[(k0 + kk) * 200 + j0 + jj];
            if (CONJW) w.y = -w.y;
            Ws[kk][jj] = w;
        }
        __syncthreads();
#pragma unroll
        for (int kk = 0; kk < 25; kk++) {
            float2 xv[2], wv[5];
#pragma unroll
            for (int mi = 0; mi < 2; mi++) xv[mi] = Xs[kk][tr + 32 * mi];
#pragma unroll
            for (int ni = 0; ni < 5; ni++) wv[ni] = Ws[kk][tc + 8 * ni];
#pragma unroll
            for (int mi = 0; mi < 2; mi++)
#pragma unroll
                for (int ni = 0; ni < 5; ni++) {
                    acc[mi][ni].x = fmaf(xv[mi].x, wv[ni].x, acc[mi][ni].x);
                    acc[mi][ni].x = fmaf(-xv[mi].y, wv[ni].y, acc[mi][ni].x);
                    acc[mi][ni].y = fmaf(xv[mi].x, wv[ni].y, acc[mi][ni].y);
                    acc[mi][ni].y = fmaf(xv[mi].y, wv[ni].x, acc[mi][ni].y);
                }
        }
        __syncthreads();
    }
#pragma unroll
    for (int mi = 0; mi < 2; mi++) {
        int rg = r0 + tr + 32 * mi;
        int i = rg % 200;
#pragma unroll
        for (int ni = 0; ni < 5; ni++) {
            int jj = j0 + tc + 8 * ni;
            float2 v = acc[mi][ni];
            if (STAGE == 2) {
                float2 hv = make_float2(hr[i * 200 + jj], hi[i * 200 + jj]);
                v = cmul(v, hv);
            } else {
                float2 p = g_ptrig[i * 200 + jj];
                float2 w = cmul(v, p);
                v = make_float2(w.x * 2.5e-5f, w.y * 2.5e-5f);  // / 200^2
            }
            C[rg * 200 + jj] = v;
        }
    }
}

// --------------------------- pixel expansion -------------------------------
// One thread per output float4 (2 complex pixels). Fully coalesced STG.128.
// Per-row floats = 2000*2 = 4000 -> 1000 float4. Each 10-pixel col block =
// 5 float4: [0,0,v,v][v,v,v,v][v,v,v,v][v,v,v,v][v,v,0,0]; rows r==0,9 zero.
__global__ void __launch_bounds__(256) expand_kernel(float4* __restrict__ out)
{
    unsigned q = blockIdx.x * 256u + threadIdx.x;   // < 32,000,000
    if (q >= 32000000u) return;
    unsigned w = q % 1000u;
    unsigned rowq = q / 1000u;
    unsigned R = rowq % 2000u;
    unsigned b = rowq / 2000u;
    unsigned r = R % 10u;
    unsigned s1 = R / 10u;
    unsigned s2 = w / 5u;
    unsigned pos = w - s2 * 5u;

    float4 v = make_float4(0.f, 0.f, 0.f, 0.f);
    if (r >= 1u && r <= 8u) {
        float2 xv = g_bufA[b * SS + s1 * 200u + s2];
        if (pos == 0u)      v = make_float4(0.f, 0.f, xv.x, xv.y);
        else if (pos == 4u) v = make_float4(xv.x, xv.y, 0.f, 0.f);
        else                v = make_float4(xv.x, xv.y, xv.x, xv.y);
    }
    out[q] = v;
}

// ------------------------------- launcher ----------------------------------
extern "C" void kernel_launch(void* const* d_in, const int* in_sizes, int n_in,
                              void* d_out, int out_size)
{
    (void)in_sizes; (void)n_in; (void)out_size;
    const float* wr   = (const float*)d_in[0];
    const float* wi   = (const float*)d_in[1];
    const float* hr   = (const float*)d_in[2];
    const float* hi   = (const float*)d_in[3];
    const float* volt = (const float*)d_in[4];
    const float* pf   = (const float*)d_in[5];
    const float* itf  = (const float*)d_in[6];
    float4* out = (float4*)d_out;

    // jax.random.key(42) = (0,42); partitionable "foldlike" split:
    //   k_i = full cipher pair of threefry((0,42), x0=0, x1=i)
    uint32_t k1a, k1b, k2a, k2b;
    threefry2x32(0u, 42u, 0u, 0u, k1a, k1b);   // k1 (phase)
    threefry2x32(0u, 42u, 0u, 1u, k2a, k2b);   // k2 (amplitude)

    init_W_kernel<<<(SS + 255) / 256, 256>>>();
    gumbel_kernel<<<SS, 256>>>(volt, pf, itf, k1a, k1b, k2a, k2b);

    gemm_left_kernel<1><<<dim3(50, 5), 256>>>(wr, wi);   // bufB = W @ X
    gemm_right_kernel<2><<<dim3(5, 50), 256>>>(hr, hi);  // bufA = (bufB@W)*h
    gemm_left_kernel<3><<<dim3(50, 5), 256>>>(wr, wi);   // bufB = Wc @ bufA
    gemm_right_kernel<4><<<dim3(5, 50), 256>>>(hr, hi);  // bufA = bufB@Wc *ptrig/S^2

    expand_kernel<<<(32000000 + 255) / 256, 256>>>(out);
}